// round 1
// baseline (speedup 1.0000x reference)
#include <cuda_runtime.h>
#include <cstdint>

#define MAXN 50000
#define MAXE 1600000

// ---- scratch (static device globals: allocation-free) ----
__device__ float g_agg[MAXN * 128];
__device__ float g_hA[MAXN * 128];
__device__ float g_hB[MAXN * 128];
__device__ int   g_src[MAXE];
__device__ int   g_dst[MAXE];
__device__ int   g_is64;

// ---------------------------------------------------------------------------
// dtype detection: edge_index may be int64 (as written) or int32 (JAX default
// x64-disabled canonicalization). Decide on-device, deterministically.
// ---------------------------------------------------------------------------
__global__ void detect_kernel(const long long* __restrict__ ei, int E_, int N_) {
    __shared__ int bad;
    if (threadIdx.x == 0) bad = 0;
    __syncthreads();
    int cnt = 0;
    for (int i = threadIdx.x; i < 512; i += blockDim.x) {
        long long v = ei[i];   // first 512 int64 words exist in both layouts
        if (v < 0 || v >= (long long)N_) cnt++;
    }
    atomicAdd(&bad, cnt);
    __syncthreads();
    if (threadIdx.x == 0) g_is64 = (bad < 256) ? 1 : 0;
}

__global__ void convert_kernel(const void* __restrict__ ei, int E_) {
    int e = blockIdx.x * blockDim.x + threadIdx.x;
    if (e >= E_) return;
    if (g_is64) {
        const long long* p = (const long long*)ei;
        g_src[e] = (int)p[e];
        g_dst[e] = (int)p[E_ + e];
    } else {
        const int* p = (const int*)ei;
        g_src[e] = p[e];
        g_dst[e] = p[E_ + e];
    }
}

__global__ void zero_kernel(int n4) {
    int i = blockIdx.x * blockDim.x + threadIdx.x;
    if (i < n4) ((float4*)g_agg)[i] = make_float4(0.f, 0.f, 0.f, 0.f);
}

// ---------------------------------------------------------------------------
// Edge kernel: one warp per edge.
//   emb = ea[e] @ We + be  (We cached in smem, 16 x D)
//   msg = relu(x[src] + emb)
//   atomicAdd into g_agg[dst]
// D in {64,128}; each lane owns D/32 contiguous channels (float2 / float4).
// ---------------------------------------------------------------------------
template <int D>
__global__ void __launch_bounds__(256) edge_kernel(
    const float* __restrict__ xp, int xs,
    const float* __restrict__ ea,
    const float* __restrict__ We, const float* __restrict__ be, int E_)
{
    __shared__ float sWe[16 * D];
    __shared__ float sbe[D];
    for (int i = threadIdx.x; i < 16 * D; i += 256) sWe[i] = We[i];
    for (int i = threadIdx.x; i < D; i += 256) sbe[i] = be[i];
    __syncthreads();

    const float* x = xp ? xp : (xs == 0 ? g_hA : g_hB);
    int lane = threadIdx.x & 31;
    int gw = (blockIdx.x * 256 + threadIdx.x) >> 5;
    int nw = (gridDim.x * 256) >> 5;

    for (int e = gw; e < E_; e += nw) {
        int src = g_src[e];
        int dst = g_dst[e];
        const float4* ea4 = (const float4*)(ea + (size_t)e * 16);
        float4 q0 = ea4[0], q1 = ea4[1], q2 = ea4[2], q3 = ea4[3];
        float eak[16] = {q0.x, q0.y, q0.z, q0.w, q1.x, q1.y, q1.z, q1.w,
                         q2.x, q2.y, q2.z, q2.w, q3.x, q3.y, q3.z, q3.w};
        if constexpr (D == 128) {
            float4 acc = ((const float4*)sbe)[lane];
            #pragma unroll
            for (int k = 0; k < 16; k++) {
                float4 w = ((const float4*)(sWe + k * 128))[lane];
                acc.x = fmaf(eak[k], w.x, acc.x);
                acc.y = fmaf(eak[k], w.y, acc.y);
                acc.z = fmaf(eak[k], w.z, acc.z);
                acc.w = fmaf(eak[k], w.w, acc.w);
            }
            float4 xv = ((const float4*)(x + (size_t)src * 128))[lane];
            float m0 = fmaxf(acc.x + xv.x, 0.f);
            float m1 = fmaxf(acc.y + xv.y, 0.f);
            float m2 = fmaxf(acc.z + xv.z, 0.f);
            float m3 = fmaxf(acc.w + xv.w, 0.f);
            float* p = g_agg + (size_t)dst * 128 + lane * 4;
            atomicAdd(p + 0, m0);
            atomicAdd(p + 1, m1);
            atomicAdd(p + 2, m2);
            atomicAdd(p + 3, m3);
        } else {  // D == 64
            float2 acc = ((const float2*)sbe)[lane];
            #pragma unroll
            for (int k = 0; k < 16; k++) {
                float2 w = ((const float2*)(sWe + k * 64))[lane];
                acc.x = fmaf(eak[k], w.x, acc.x);
                acc.y = fmaf(eak[k], w.y, acc.y);
            }
            float2 xv = ((const float2*)(x + (size_t)src * 64))[lane];
            float m0 = fmaxf(acc.x + xv.x, 0.f);
            float m1 = fmaxf(acc.y + xv.y, 0.f);
            float* p = g_agg + (size_t)dst * 64 + lane * 2;
            atomicAdd(p + 0, m0);
            atomicAdd(p + 1, m1);
        }
    }
}

// ---------------------------------------------------------------------------
// Fused MLP kernel (persistent blocks, W1/W2/b resident in smem):
//   h = x + agg ;  out = relu( relu(h@W1 + b1) @ W2 + b2 )
// 64-row tiles, 256 threads, each thread computes 8 rows x 4 cols.
// ---------------------------------------------------------------------------
template <int DIN>
__global__ void __launch_bounds__(256, 1) mlp_kernel(
    const float* __restrict__ xp, int xs, int os,
    const float* __restrict__ W1, const float* __restrict__ b1,
    const float* __restrict__ W2, const float* __restrict__ b2, int N_)
{
    extern __shared__ float sm[];
    float* sW1 = sm;                    // DIN*128
    float* sW2 = sW1 + DIN * 128;       // 128*128
    float* sb1 = sW2 + 16384;           // 128
    float* sb2 = sb1 + 128;             // 128
    float* sH  = sb2 + 128;             // 64*DIN
    float* sT  = sH + 64 * DIN;         // 64*128

    int tid = threadIdx.x;
    for (int i = tid; i < DIN * 128; i += 256) sW1[i] = W1[i];
    for (int i = tid; i < 16384; i += 256) sW2[i] = W2[i];
    if (tid < 128) { sb1[tid] = b1[tid]; sb2[tid] = b2[tid]; }
    __syncthreads();

    const float* xin = xp ? xp : (xs == 0 ? g_hA : g_hB);
    float* outp = (os == 0) ? g_hA : g_hB;

    int tx = tid & 31;   // col group: cols tx*4 .. tx*4+3
    int ty = tid >> 5;   // row group: rows ty*8 .. ty*8+7

    const int ntiles = (N_ + 63) / 64;
    for (int tile = blockIdx.x; tile < ntiles; tile += gridDim.x) {
        int base = tile * 64;

        // load sH = x + agg (float4, row-guarded)
        constexpr int C4 = DIN / 4;
        for (int i4 = tid; i4 < 64 * C4; i4 += 256) {
            int r = i4 / C4;
            int c4 = i4 - r * C4;
            int gr = base + r;
            float4 v = make_float4(0.f, 0.f, 0.f, 0.f);
            if (gr < N_) {
                float4 a = ((const float4*)xin)[(size_t)gr * C4 + c4];
                float4 b = ((const float4*)g_agg)[(size_t)gr * C4 + c4];
                v = make_float4(a.x + b.x, a.y + b.y, a.z + b.z, a.w + b.w);
            }
            ((float4*)sH)[i4] = v;
        }
        __syncthreads();

        // phase 1: t = relu(h @ W1 + b1)
        {
            float4 acc[8];
            float bx = sb1[tx * 4 + 0], by = sb1[tx * 4 + 1];
            float bz = sb1[tx * 4 + 2], bw = sb1[tx * 4 + 3];
            #pragma unroll
            for (int r = 0; r < 8; r++) acc[r] = make_float4(bx, by, bz, bw);
            #pragma unroll 4
            for (int k = 0; k < DIN; k++) {
                float4 w = ((const float4*)(sW1 + k * 128))[tx];
                #pragma unroll
                for (int r = 0; r < 8; r++) {
                    float a = sH[(ty * 8 + r) * DIN + k];
                    acc[r].x = fmaf(a, w.x, acc[r].x);
                    acc[r].y = fmaf(a, w.y, acc[r].y);
                    acc[r].z = fmaf(a, w.z, acc[r].z);
                    acc[r].w = fmaf(a, w.w, acc[r].w);
                }
            }
            #pragma unroll
            for (int r = 0; r < 8; r++) {
                float4 v = make_float4(fmaxf(acc[r].x, 0.f), fmaxf(acc[r].y, 0.f),
                                       fmaxf(acc[r].z, 0.f), fmaxf(acc[r].w, 0.f));
                ((float4*)(sT + (ty * 8 + r) * 128))[tx] = v;
            }
        }
        __syncthreads();

        // phase 2: out = relu(t @ W2 + b2)
        {
            float4 acc[8];
            float bx = sb2[tx * 4 + 0], by = sb2[tx * 4 + 1];
            float bz = sb2[tx * 4 + 2], bw = sb2[tx * 4 + 3];
            #pragma unroll
            for (int r = 0; r < 8; r++) acc[r] = make_float4(bx, by, bz, bw);
            #pragma unroll 4
            for (int k = 0; k < 128; k++) {
                float4 w = ((const float4*)(sW2 + k * 128))[tx];
                #pragma unroll
                for (int r = 0; r < 8; r++) {
                    float a = sT[(ty * 8 + r) * 128 + k];
                    acc[r].x = fmaf(a, w.x, acc[r].x);
                    acc[r].y = fmaf(a, w.y, acc[r].y);
                    acc[r].z = fmaf(a, w.z, acc[r].z);
                    acc[r].w = fmaf(a, w.w, acc[r].w);
                }
            }
            #pragma unroll
            for (int r = 0; r < 8; r++) {
                int gr = base + ty * 8 + r;
                if (gr < N_) {
                    float4 v = make_float4(fmaxf(acc[r].x, 0.f), fmaxf(acc[r].y, 0.f),
                                           fmaxf(acc[r].z, 0.f), fmaxf(acc[r].w, 0.f));
                    ((float4*)(outp + (size_t)gr * 128))[tx] = v;
                }
            }
        }
        __syncthreads();
    }
}

// ---------------------------------------------------------------------------
// Final: out[n] = sigmoid(h[n] . Wlin + blin). One warp per node.
// ---------------------------------------------------------------------------
__global__ void __launch_bounds__(256) final_kernel(
    int hs, const float* __restrict__ Wlin, const float* __restrict__ blin,
    float* __restrict__ out, int N_)
{
    __shared__ float sw[128];
    if (threadIdx.x < 128) sw[threadIdx.x] = Wlin[threadIdx.x];
    __syncthreads();
    const float* h = (hs == 0) ? g_hA : g_hB;
    int lane = threadIdx.x & 31;
    int warp = (blockIdx.x * 256 + threadIdx.x) >> 5;
    int nw = (gridDim.x * 256) >> 5;
    float bl = blin[0];
    for (int n = warp; n < N_; n += nw) {
        float4 hv = ((const float4*)(h + (size_t)n * 128))[lane];
        float4 wv = ((const float4*)sw)[lane];
        float v = hv.x * wv.x + hv.y * wv.y + hv.z * wv.z + hv.w * wv.w;
        #pragma unroll
        for (int o = 16; o; o >>= 1) v += __shfl_xor_sync(0xFFFFFFFFu, v, o);
        if (lane == 0) out[n] = 1.f / (1.f + expf(-(v + bl)));
    }
}

// ---------------------------------------------------------------------------
extern "C" void kernel_launch(void* const* d_in, const int* in_sizes, int n_in,
                              void* d_out, int out_size)
{
    const float* x   = (const float*)d_in[0];
    const void*  ei  = d_in[1];
    const float* ea  = (const float*)d_in[2];
    const float* We0 = (const float*)d_in[3];
    const float* be0 = (const float*)d_in[4];
    const float* W10 = (const float*)d_in[5];
    const float* b10 = (const float*)d_in[6];
    const float* W20 = (const float*)d_in[7];
    const float* b20 = (const float*)d_in[8];
    const float* We1 = (const float*)d_in[9];
    const float* be1 = (const float*)d_in[10];
    const float* W11 = (const float*)d_in[11];
    const float* b11 = (const float*)d_in[12];
    const float* W21 = (const float*)d_in[13];
    const float* b21 = (const float*)d_in[14];
    const float* We2 = (const float*)d_in[15];
    const float* be2 = (const float*)d_in[16];
    const float* W12 = (const float*)d_in[17];
    const float* b12 = (const float*)d_in[18];
    const float* W22 = (const float*)d_in[19];
    const float* b22 = (const float*)d_in[20];
    const float* Wln = (const float*)d_in[21];
    const float* bln = (const float*)d_in[22];

    int N_ = in_sizes[0] / 64;
    int E_ = in_sizes[2] / 16;

    constexpr int SMEM64  = (64 * 128 + 16384 + 256 + 64 * 64 + 64 * 128) * 4;
    constexpr int SMEM128 = (128 * 128 + 16384 + 256 + 64 * 128 + 64 * 128) * 4;
    cudaFuncSetAttribute(mlp_kernel<64>,  cudaFuncAttributeMaxDynamicSharedMemorySize, SMEM64);
    cudaFuncSetAttribute(mlp_kernel<128>, cudaFuncAttributeMaxDynamicSharedMemorySize, SMEM128);

    const int EDGE_BLKS = 2368;

    // normalize edge index dtype -> g_src/g_dst (int32)
    detect_kernel<<<1, 256>>>((const long long*)ei, E_, N_);
    convert_kernel<<<(E_ + 255) / 256, 256>>>(ei, E_);

    // ---- layer 0 (d = 64) ----
    zero_kernel<<<(N_ * 16 + 255) / 256, 256>>>(N_ * 16);
    edge_kernel<64><<<EDGE_BLKS, 256>>>(x, 0, ea, We0, be0, E_);
    mlp_kernel<64><<<148, 256, SMEM64>>>(x, 0, /*out=hA*/0, W10, b10, W20, b20, N_);

    // ---- layer 1 (d = 128) ----
    zero_kernel<<<(N_ * 32 + 255) / 256, 256>>>(N_ * 32);
    edge_kernel<128><<<EDGE_BLKS, 256>>>(nullptr, /*x=hA*/0, ea, We1, be1, E_);
    mlp_kernel<128><<<148, 256, SMEM128>>>(nullptr, 0, /*out=hB*/1, W11, b11, W21, b21, N_);

    // ---- layer 2 (d = 128) ----
    zero_kernel<<<(N_ * 32 + 255) / 256, 256>>>(N_ * 32);
    edge_kernel<128><<<EDGE_BLKS, 256>>>(nullptr, /*x=hB*/1, ea, We2, be2, E_);
    mlp_kernel<128><<<148, 256, SMEM128>>>(nullptr, 1, /*out=hA*/0, W12, b12, W22, b22, N_);

    // ---- final linear + sigmoid ----
    final_kernel<<<(N_ + 7) / 8, 256>>>(0, Wln, bln, (float*)d_out, N_);
}

// round 2
// speedup vs baseline: 1.4398x; 1.4398x over previous
#include <cuda_runtime.h>
#include <cstdint>

#define MAXN 50000
#define MAXE 1600000

// ---- scratch (static device globals: allocation-free) ----
__device__ float g_h [MAXN * 128];   // gather output: h = x + sum(relu(...))
__device__ float g_hA[MAXN * 128];
__device__ float g_hB[MAXN * 128];
__device__ int   g_src[MAXE];
__device__ int   g_dst[MAXE];
__device__ int   g_deg[MAXN];
__device__ int   g_cur[MAXN];
__device__ int   g_rowptr[MAXN + 1];
__device__ int   g_bsums[128];
__device__ int   g_srcs[MAXE];          // src sorted by dst
__device__ float g_eas[(size_t)MAXE * 16];  // edge_attr sorted by dst
__device__ int   g_is64;

// ---------------------------------------------------------------------------
// dtype detection: edge_index may be int64 or int32 (JAX x64-off canonicalizes)
// ---------------------------------------------------------------------------
__global__ void detect_kernel(const long long* __restrict__ ei, int E_, int N_) {
    __shared__ int bad;
    if (threadIdx.x == 0) bad = 0;
    __syncthreads();
    int cnt = 0;
    for (int i = threadIdx.x; i < 512; i += blockDim.x) {
        long long v = ei[i];
        if (v < 0 || v >= (long long)N_) cnt++;
    }
    atomicAdd(&bad, cnt);
    __syncthreads();
    if (threadIdx.x == 0) g_is64 = (bad < 256) ? 1 : 0;
}

__global__ void zero_aux_kernel(int N_) {
    int i = blockIdx.x * blockDim.x + threadIdx.x;
    if (i < N_) { g_deg[i] = 0; g_cur[i] = 0; }
}

// convert to int32 + histogram of dst
__global__ void convert_hist_kernel(const void* __restrict__ ei, int E_) {
    int e = blockIdx.x * blockDim.x + threadIdx.x;
    if (e >= E_) return;
    int s, d;
    if (g_is64) {
        const long long* p = (const long long*)ei;
        s = (int)p[e]; d = (int)p[E_ + e];
    } else {
        const int* p = (const int*)ei;
        s = p[e]; d = p[E_ + e];
    }
    g_src[e] = s;
    g_dst[e] = d;
    atomicAdd(&g_deg[d], 1);
}

// ---- exclusive scan of g_deg[0..N) into g_rowptr (3 kernels) ----
__global__ void scan1_kernel(int N_) {
    __shared__ int sh[1024];
    int tid = threadIdx.x;
    int i = blockIdx.x * 1024 + tid;
    int v = (i < N_) ? g_deg[i] : 0;
    sh[tid] = v;
    __syncthreads();
    #pragma unroll
    for (int off = 1; off < 1024; off <<= 1) {
        int t = (tid >= off) ? sh[tid - off] : 0;
        __syncthreads();
        sh[tid] += t;
        __syncthreads();
    }
    if (i < N_) g_rowptr[i + 1] = sh[tid];   // inclusive -> rowptr[i+1]
    if (tid == 1023) g_bsums[blockIdx.x] = sh[1023];
    if (i == 0) g_rowptr[0] = 0;
}

__global__ void scan2_kernel(int nb) {
    if (threadIdx.x == 0) {
        int run = 0;
        for (int b = 0; b < nb; b++) {
            int v = g_bsums[b];
            g_bsums[b] = run;   // exclusive
            run += v;
        }
    }
}

__global__ void scan3_kernel(int N_) {
    int i = blockIdx.x * 1024 + threadIdx.x;
    if (i < N_ && blockIdx.x > 0) g_rowptr[i + 1] += g_bsums[blockIdx.x];
}

// scatter edges into dst-sorted order (src id + edge_attr)
__global__ void scatter_kernel(const float* __restrict__ ea, int E_) {
    int e = blockIdx.x * blockDim.x + threadIdx.x;
    if (e >= E_) return;
    int d = g_dst[e];
    int pos = g_rowptr[d] + atomicAdd(&g_cur[d], 1);
    g_srcs[pos] = g_src[e];
    const float4* in4 = (const float4*)(ea + (size_t)e * 16);
    float4* out4 = (float4*)(g_eas + (size_t)pos * 16);
    out4[0] = in4[0]; out4[1] = in4[1]; out4[2] = in4[2]; out4[3] = in4[3];
}

// ---------------------------------------------------------------------------
// Gather kernel: one warp per node, no atomics.
//   h[n] = x[n] + sum_{e in in(n)} relu( x[src_e] + ea_e @ We + be )
// We held entirely in registers (16 x D/32 per lane).
// ---------------------------------------------------------------------------
template <int D>
__global__ void __launch_bounds__(256, 2) gather_kernel(
    const float* __restrict__ xp, int xs,
    const float* __restrict__ We, const float* __restrict__ be, int N_)
{
    const float* x = xp ? xp : (xs == 0 ? g_hA : g_hB);
    int lane = threadIdx.x & 31;
    int n = (blockIdx.x * 256 + threadIdx.x) >> 5;
    if (n >= N_) return;

    int beg = g_rowptr[n];
    int end = g_rowptr[n + 1];

    if constexpr (D == 128) {
        float4 w[16];
        #pragma unroll
        for (int k = 0; k < 16; k++)
            w[k] = ((const float4*)(We + k * 128))[lane];
        float4 bias = ((const float4*)be)[lane];
        float4 acc = make_float4(0.f, 0.f, 0.f, 0.f);

        for (int e = beg; e < end; e++) {
            int src = g_srcs[e];
            const float4* ea4 = (const float4*)(g_eas + (size_t)e * 16);
            float4 q0 = ea4[0], q1 = ea4[1], q2 = ea4[2], q3 = ea4[3];
            float eak[16] = {q0.x, q0.y, q0.z, q0.w, q1.x, q1.y, q1.z, q1.w,
                             q2.x, q2.y, q2.z, q2.w, q3.x, q3.y, q3.z, q3.w};
            // two independent partial sums to shorten the FMA chain
            float4 s0 = bias, s1 = make_float4(0.f, 0.f, 0.f, 0.f);
            #pragma unroll
            for (int k = 0; k < 8; k++) {
                s0.x = fmaf(eak[k], w[k].x, s0.x);
                s0.y = fmaf(eak[k], w[k].y, s0.y);
                s0.z = fmaf(eak[k], w[k].z, s0.z);
                s0.w = fmaf(eak[k], w[k].w, s0.w);
            }
            #pragma unroll
            for (int k = 8; k < 16; k++) {
                s1.x = fmaf(eak[k], w[k].x, s1.x);
                s1.y = fmaf(eak[k], w[k].y, s1.y);
                s1.z = fmaf(eak[k], w[k].z, s1.z);
                s1.w = fmaf(eak[k], w[k].w, s1.w);
            }
            float4 xv = ((const float4*)(x + (size_t)src * 128))[lane];
            acc.x += fmaxf(s0.x + s1.x + xv.x, 0.f);
            acc.y += fmaxf(s0.y + s1.y + xv.y, 0.f);
            acc.z += fmaxf(s0.z + s1.z + xv.z, 0.f);
            acc.w += fmaxf(s0.w + s1.w + xv.w, 0.f);
        }
        float4 xn = ((const float4*)(x + (size_t)n * 128))[lane];
        float4 out = make_float4(acc.x + xn.x, acc.y + xn.y,
                                 acc.z + xn.z, acc.w + xn.w);
        ((float4*)(g_h + (size_t)n * 128))[lane] = out;
    } else {  // D == 64
        float2 w[16];
        #pragma unroll
        for (int k = 0; k < 16; k++)
            w[k] = ((const float2*)(We + k * 64))[lane];
        float2 bias = ((const float2*)be)[lane];
        float2 acc = make_float2(0.f, 0.f);

        for (int e = beg; e < end; e++) {
            int src = g_srcs[e];
            const float4* ea4 = (const float4*)(g_eas + (size_t)e * 16);
            float4 q0 = ea4[0], q1 = ea4[1], q2 = ea4[2], q3 = ea4[3];
            float eak[16] = {q0.x, q0.y, q0.z, q0.w, q1.x, q1.y, q1.z, q1.w,
                             q2.x, q2.y, q2.z, q2.w, q3.x, q3.y, q3.z, q3.w};
            float2 s0 = bias, s1 = make_float2(0.f, 0.f);
            #pragma unroll
            for (int k = 0; k < 8; k++) {
                s0.x = fmaf(eak[k], w[k].x, s0.x);
                s0.y = fmaf(eak[k], w[k].y, s0.y);
            }
            #pragma unroll
            for (int k = 8; k < 16; k++) {
                s1.x = fmaf(eak[k], w[k].x, s1.x);
                s1.y = fmaf(eak[k], w[k].y, s1.y);
            }
            float2 xv = ((const float2*)(x + (size_t)src * 64))[lane];
            acc.x += fmaxf(s0.x + s1.x + xv.x, 0.f);
            acc.y += fmaxf(s0.y + s1.y + xv.y, 0.f);
        }
        float2 xn = ((const float2*)(x + (size_t)n * 64))[lane];
        ((float2*)(g_h + (size_t)n * 64))[lane] = make_float2(acc.x + xn.x, acc.y + xn.y);
    }
}

// ---------------------------------------------------------------------------
// Fused MLP kernel (persistent blocks, W1/W2 resident in smem):
//   out = relu( relu(h@W1 + b1) @ W2 + b2 ),  h read from g_h
// ---------------------------------------------------------------------------
template <int DIN>
__global__ void __launch_bounds__(256, 1) mlp_kernel(
    int os,
    const float* __restrict__ W1, const float* __restrict__ b1,
    const float* __restrict__ W2, const float* __restrict__ b2, int N_)
{
    extern __shared__ float sm[];
    float* sW1 = sm;                    // DIN*128
    float* sW2 = sW1 + DIN * 128;       // 128*128
    float* sb1 = sW2 + 16384;           // 128
    float* sb2 = sb1 + 128;             // 128
    float* sH  = sb2 + 128;             // 64*DIN
    float* sT  = sH + 64 * DIN;         // 64*128

    int tid = threadIdx.x;
    for (int i = tid; i < DIN * 128; i += 256) sW1[i] = W1[i];
    for (int i = tid; i < 16384; i += 256) sW2[i] = W2[i];
    if (tid < 128) { sb1[tid] = b1[tid]; sb2[tid] = b2[tid]; }
    __syncthreads();

    float* outp = (os == 0) ? g_hA : g_hB;

    int tx = tid & 31;   // col group: cols tx*4 .. tx*4+3
    int ty = tid >> 5;   // row group: rows ty*8 .. ty*8+7

    const int ntiles = (N_ + 63) / 64;
    for (int tile = blockIdx.x; tile < ntiles; tile += gridDim.x) {
        int base = tile * 64;

        // load sH from g_h (float4, row-guarded)
        constexpr int C4 = DIN / 4;
        for (int i4 = tid; i4 < 64 * C4; i4 += 256) {
            int r = i4 / C4;
            int c4 = i4 - r * C4;
            int gr = base + r;
            float4 v = make_float4(0.f, 0.f, 0.f, 0.f);
            if (gr < N_) v = ((const float4*)g_h)[(size_t)gr * C4 + c4];
            ((float4*)sH)[i4] = v;
        }
        __syncthreads();

        // phase 1: t = relu(h @ W1 + b1)
        {
            float4 acc[8];
            float bx = sb1[tx * 4 + 0], by = sb1[tx * 4 + 1];
            float bz = sb1[tx * 4 + 2], bw = sb1[tx * 4 + 3];
            #pragma unroll
            for (int r = 0; r < 8; r++) acc[r] = make_float4(bx, by, bz, bw);
            #pragma unroll 2
            for (int k4 = 0; k4 < DIN / 4; k4++) {
                float4 a[8];
                #pragma unroll
                for (int r = 0; r < 8; r++)
                    a[r] = ((const float4*)(sH + (ty * 8 + r) * DIN))[k4];
                #pragma unroll
                for (int j = 0; j < 4; j++) {
                    float4 wv = ((const float4*)(sW1 + (k4 * 4 + j) * 128))[tx];
                    #pragma unroll
                    for (int r = 0; r < 8; r++) {
                        float av = (j == 0) ? a[r].x : (j == 1) ? a[r].y : (j == 2) ? a[r].z : a[r].w;
                        acc[r].x = fmaf(av, wv.x, acc[r].x);
                        acc[r].y = fmaf(av, wv.y, acc[r].y);
                        acc[r].z = fmaf(av, wv.z, acc[r].z);
                        acc[r].w = fmaf(av, wv.w, acc[r].w);
                    }
                }
            }
            #pragma unroll
            for (int r = 0; r < 8; r++) {
                float4 v = make_float4(fmaxf(acc[r].x, 0.f), fmaxf(acc[r].y, 0.f),
                                       fmaxf(acc[r].z, 0.f), fmaxf(acc[r].w, 0.f));
                ((float4*)(sT + (ty * 8 + r) * 128))[tx] = v;
            }
        }
        __syncthreads();

        // phase 2: out = relu(t @ W2 + b2)
        {
            float4 acc[8];
            float bx = sb2[tx * 4 + 0], by = sb2[tx * 4 + 1];
            float bz = sb2[tx * 4 + 2], bw = sb2[tx * 4 + 3];
            #pragma unroll
            for (int r = 0; r < 8; r++) acc[r] = make_float4(bx, by, bz, bw);
            #pragma unroll 2
            for (int k4 = 0; k4 < 32; k4++) {
                float4 a[8];
                #pragma unroll
                for (int r = 0; r < 8; r++)
                    a[r] = ((const float4*)(sT + (ty * 8 + r) * 128))[k4];
                #pragma unroll
                for (int j = 0; j < 4; j++) {
                    float4 wv = ((const float4*)(sW2 + (k4 * 4 + j) * 128))[tx];
                    #pragma unroll
                    for (int r = 0; r < 8; r++) {
                        float av = (j == 0) ? a[r].x : (j == 1) ? a[r].y : (j == 2) ? a[r].z : a[r].w;
                        acc[r].x = fmaf(av, wv.x, acc[r].x);
                        acc[r].y = fmaf(av, wv.y, acc[r].y);
                        acc[r].z = fmaf(av, wv.z, acc[r].z);
                        acc[r].w = fmaf(av, wv.w, acc[r].w);
                    }
                }
            }
            #pragma unroll
            for (int r = 0; r < 8; r++) {
                int gr = base + ty * 8 + r;
                if (gr < N_) {
                    float4 v = make_float4(fmaxf(acc[r].x, 0.f), fmaxf(acc[r].y, 0.f),
                                           fmaxf(acc[r].z, 0.f), fmaxf(acc[r].w, 0.f));
                    ((float4*)(outp + (size_t)gr * 128))[tx] = v;
                }
            }
        }
        __syncthreads();
    }
}

// ---------------------------------------------------------------------------
// Final: out[n] = sigmoid(h[n] . Wlin + blin). One warp per node.
// ---------------------------------------------------------------------------
__global__ void __launch_bounds__(256) final_kernel(
    int hs, const float* __restrict__ Wlin, const float* __restrict__ blin,
    float* __restrict__ out, int N_)
{
    __shared__ float sw[128];
    if (threadIdx.x < 128) sw[threadIdx.x] = Wlin[threadIdx.x];
    __syncthreads();
    const float* h = (hs == 0) ? g_hA : g_hB;
    int lane = threadIdx.x & 31;
    int warp = (blockIdx.x * 256 + threadIdx.x) >> 5;
    int nw = (gridDim.x * 256) >> 5;
    float bl = blin[0];
    for (int n = warp; n < N_; n += nw) {
        float4 hv = ((const float4*)(h + (size_t)n * 128))[lane];
        float4 wv = ((const float4*)sw)[lane];
        float v = hv.x * wv.x + hv.y * wv.y + hv.z * wv.z + hv.w * wv.w;
        #pragma unroll
        for (int o = 16; o; o >>= 1) v += __shfl_xor_sync(0xFFFFFFFFu, v, o);
        if (lane == 0) out[n] = 1.f / (1.f + expf(-(v + bl)));
    }
}

// ---------------------------------------------------------------------------
extern "C" void kernel_launch(void* const* d_in, const int* in_sizes, int n_in,
                              void* d_out, int out_size)
{
    const float* x   = (const float*)d_in[0];
    const void*  ei  = d_in[1];
    const float* ea  = (const float*)d_in[2];
    const float* We0 = (const float*)d_in[3];
    const float* be0 = (const float*)d_in[4];
    const float* W10 = (const float*)d_in[5];
    const float* b10 = (const float*)d_in[6];
    const float* W20 = (const float*)d_in[7];
    const float* b20 = (const float*)d_in[8];
    const float* We1 = (const float*)d_in[9];
    const float* be1 = (const float*)d_in[10];
    const float* W11 = (const float*)d_in[11];
    const float* b11 = (const float*)d_in[12];
    const float* W21 = (const float*)d_in[13];
    const float* b21 = (const float*)d_in[14];
    const float* We2 = (const float*)d_in[15];
    const float* be2 = (const float*)d_in[16];
    const float* W12 = (const float*)d_in[17];
    const float* b12 = (const float*)d_in[18];
    const float* W22 = (const float*)d_in[19];
    const float* b22 = (const float*)d_in[20];
    const float* Wln = (const float*)d_in[21];
    const float* bln = (const float*)d_in[22];

    int N_ = in_sizes[0] / 64;
    int E_ = in_sizes[2] / 16;

    constexpr int SMEM64  = (64 * 128 + 16384 + 256 + 64 * 64 + 64 * 128) * 4;
    constexpr int SMEM128 = (128 * 128 + 16384 + 256 + 64 * 128 + 64 * 128) * 4;
    cudaFuncSetAttribute(mlp_kernel<64>,  cudaFuncAttributeMaxDynamicSharedMemorySize, SMEM64);
    cudaFuncSetAttribute(mlp_kernel<128>, cudaFuncAttributeMaxDynamicSharedMemorySize, SMEM128);

    int ebc = (E_ + 255) / 256;        // edge-count blocks
    int nb  = (N_ + 1023) / 1024;      // scan blocks
    int gwb = (N_ * 32 + 255) / 256;   // warp-per-node blocks

    // ---- CSR build (once per call; ea permutation shared by all 3 layers) ----
    detect_kernel<<<1, 256>>>((const long long*)ei, E_, N_);
    zero_aux_kernel<<<(N_ + 255) / 256, 256>>>(N_);
    convert_hist_kernel<<<ebc, 256>>>(ei, E_);
    scan1_kernel<<<nb, 1024>>>(N_);
    scan2_kernel<<<1, 32>>>(nb);
    scan3_kernel<<<nb, 1024>>>(N_);
    scatter_kernel<<<ebc, 256>>>(ea, E_);

    // ---- layer 0 (d = 64) ----
    gather_kernel<64><<<gwb, 256>>>(x, 0, We0, be0, N_);
    mlp_kernel<64><<<148, 256, SMEM64>>>(/*out=hA*/0, W10, b10, W20, b20, N_);

    // ---- layer 1 (d = 128) ----
    gather_kernel<128><<<gwb, 256>>>(nullptr, /*x=hA*/0, We1, be1, N_);
    mlp_kernel<128><<<148, 256, SMEM128>>>(/*out=hB*/1, W11, b11, W21, b21, N_);

    // ---- layer 2 (d = 128) ----
    gather_kernel<128><<<gwb, 256>>>(nullptr, /*x=hB*/1, We2, be2, N_);
    mlp_kernel<128><<<148, 256, SMEM128>>>(/*out=hA*/0, W12, b12, W22, b22, N_);

    // ---- final linear + sigmoid ----
    final_kernel<<<(N_ + 7) / 8, 256>>>(0, Wln, bln, (float*)d_out, N_);
}

// round 3
// speedup vs baseline: 1.5058x; 1.0459x over previous
#include <cuda_runtime.h>
#include <cstdint>

#define MAXN 50000
#define MAXE 1600000

// ---- scratch (static device globals: allocation-free) ----
__device__ float g_h [MAXN * 128];   // gather output: h = x + sum(relu(...))
__device__ float g_hA[MAXN * 128];
__device__ float g_hB[MAXN * 128];
__device__ int   g_src[MAXE];
__device__ int   g_dst[MAXE];
__device__ int   g_deg[MAXN];
__device__ int   g_cur[MAXN];
__device__ int   g_rowptr[MAXN + 1];
__device__ int   g_bsums[128];
__device__ int   g_srcs[MAXE];              // src sorted by dst
__device__ float g_eas[(size_t)MAXE * 16];  // edge_attr sorted by dst
__device__ int   g_is64;

// ---- packed f32x2 helpers (sm_100+: 2x fp32 FMA throughput, IEEE-exact) ----
typedef unsigned long long u64;

__device__ __forceinline__ u64 pack2(float lo, float hi) {
    u64 r;
    asm("mov.b64 %0, {%1, %2};" : "=l"(r) : "f"(lo), "f"(hi));
    return r;
}
__device__ __forceinline__ void unpack2(u64 v, float& lo, float& hi) {
    asm("mov.b64 {%0, %1}, %2;" : "=f"(lo), "=f"(hi) : "l"(v));
}
__device__ __forceinline__ u64 ffma2(u64 a, u64 b, u64 c) {
    u64 d;
    asm("fma.rn.f32x2 %0, %1, %2, %3;" : "=l"(d) : "l"(a), "l"(b), "l"(c));
    return d;
}

// ---------------------------------------------------------------------------
// dtype detection: edge_index may be int64 or int32 (JAX x64-off canonicalizes)
// ---------------------------------------------------------------------------
__global__ void detect_kernel(const long long* __restrict__ ei, int E_, int N_) {
    __shared__ int bad;
    if (threadIdx.x == 0) bad = 0;
    __syncthreads();
    int cnt = 0;
    for (int i = threadIdx.x; i < 512; i += blockDim.x) {
        long long v = ei[i];
        if (v < 0 || v >= (long long)N_) cnt++;
    }
    atomicAdd(&bad, cnt);
    __syncthreads();
    if (threadIdx.x == 0) g_is64 = (bad < 256) ? 1 : 0;
}

__global__ void zero_aux_kernel(int N_) {
    int i = blockIdx.x * blockDim.x + threadIdx.x;
    if (i < N_) { g_deg[i] = 0; g_cur[i] = 0; }
}

__global__ void convert_hist_kernel(const void* __restrict__ ei, int E_) {
    int e = blockIdx.x * blockDim.x + threadIdx.x;
    if (e >= E_) return;
    int s, d;
    if (g_is64) {
        const long long* p = (const long long*)ei;
        s = (int)p[e]; d = (int)p[E_ + e];
    } else {
        const int* p = (const int*)ei;
        s = p[e]; d = p[E_ + e];
    }
    g_src[e] = s;
    g_dst[e] = d;
    atomicAdd(&g_deg[d], 1);
}

// ---- exclusive scan of g_deg[0..N) into g_rowptr ----
__global__ void scan1_kernel(int N_) {
    __shared__ int sh[1024];
    int tid = threadIdx.x;
    int i = blockIdx.x * 1024 + tid;
    int v = (i < N_) ? g_deg[i] : 0;
    sh[tid] = v;
    __syncthreads();
    #pragma unroll
    for (int off = 1; off < 1024; off <<= 1) {
        int t = (tid >= off) ? sh[tid - off] : 0;
        __syncthreads();
        sh[tid] += t;
        __syncthreads();
    }
    if (i < N_) g_rowptr[i + 1] = sh[tid];
    if (tid == 1023) g_bsums[blockIdx.x] = sh[1023];
    if (i == 0) g_rowptr[0] = 0;
}

__global__ void scan2_kernel(int nb) {
    if (threadIdx.x == 0) {
        int run = 0;
        for (int b = 0; b < nb; b++) { int v = g_bsums[b]; g_bsums[b] = run; run += v; }
    }
}

__global__ void scan3_kernel(int N_) {
    int i = blockIdx.x * 1024 + threadIdx.x;
    if (i < N_ && blockIdx.x > 0) g_rowptr[i + 1] += g_bsums[blockIdx.x];
}

__global__ void scatter_kernel(const float* __restrict__ ea, int E_) {
    int e = blockIdx.x * blockDim.x + threadIdx.x;
    if (e >= E_) return;
    int d = g_dst[e];
    int pos = g_rowptr[d] + atomicAdd(&g_cur[d], 1);
    g_srcs[pos] = g_src[e];
    const float4* in4 = (const float4*)(ea + (size_t)e * 16);
    float4* out4 = (float4*)(g_eas + (size_t)pos * 16);
    out4[0] = in4[0]; out4[1] = in4[1]; out4[2] = in4[2]; out4[3] = in4[3];
}

// ---------------------------------------------------------------------------
// Gather kernel: one warp per node, no atomics, FFMA2-packed over K (ED=16).
//   h[n] = x[n] + sum_{e in in(n)} relu( x[src_e] + ea_e @ We + be )
// Weight pairs (We[2k][d], We[2k+1][d]) prepacked in registers; ea pairs load
// directly as u64 from the dst-sorted edge_attr.
// ---------------------------------------------------------------------------
template <int D>
__global__ void __launch_bounds__(256) gather_kernel(
    const float* __restrict__ xp, int xs,
    const float* __restrict__ We, const float* __restrict__ be, int N_)
{
    const float* x = xp ? xp : (xs == 0 ? g_hA : g_hB);
    int lane = threadIdx.x & 31;
    int n = (blockIdx.x * 256 + threadIdx.x) >> 5;
    if (n >= N_) return;

    constexpr int C = D / 32;   // channels per lane: 4 (D=128) or 2 (D=64)

    // prepack weight pairs: wp[k2][j] = (We[2k2][ch], We[2k2+1][ch])
    u64 wp[8][C];
    #pragma unroll
    for (int k2 = 0; k2 < 8; k2++)
        #pragma unroll
        for (int j = 0; j < C; j++) {
            int ch = lane * C + j;
            wp[k2][j] = pack2(We[(2 * k2) * D + ch], We[(2 * k2 + 1) * D + ch]);
        }
    float bias[C];
    #pragma unroll
    for (int j = 0; j < C; j++) bias[j] = be[lane * C + j];

    int beg = g_rowptr[n];
    int end = g_rowptr[n + 1];

    float acc[C];
    #pragma unroll
    for (int j = 0; j < C; j++) acc[j] = 0.f;

    for (int e = beg; e < end; e++) {
        int src = g_srcs[e];
        // x gather: issue early
        float xv[C];
        if constexpr (C == 4) {
            float4 t = ((const float4*)(x + (size_t)src * D))[lane];
            xv[0] = t.x; xv[1] = t.y; xv[2] = t.z; xv[3] = t.w;
        } else {
            float2 t = ((const float2*)(x + (size_t)src * D))[lane];
            xv[0] = t.x; xv[1] = t.y;
        }
        // ea row: 16 floats = 8 k-pairs, broadcast loads
        const ulonglong2* ep2 = (const ulonglong2*)(g_eas + (size_t)e * 16);
        ulonglong2 p0 = ep2[0], p1 = ep2[1], p2 = ep2[2], p3 = ep2[3];
        u64 ep[8] = {p0.x, p0.y, p1.x, p1.y, p2.x, p2.y, p3.x, p3.y};

        u64 s[C];
        #pragma unroll
        for (int j = 0; j < C; j++) s[j] = 0ULL;
        #pragma unroll
        for (int k2 = 0; k2 < 8; k2++)
            #pragma unroll
            for (int j = 0; j < C; j++)
                s[j] = ffma2(ep[k2], wp[k2][j], s[j]);

        #pragma unroll
        for (int j = 0; j < C; j++) {
            float lo, hi;
            unpack2(s[j], lo, hi);
            float t = lo + hi + (bias[j] + xv[j]);
            acc[j] += fmaxf(t, 0.f);
        }
    }

    if constexpr (C == 4) {
        float4 xn = ((const float4*)(x + (size_t)n * D))[lane];
        float4 out = make_float4(acc[0] + xn.x, acc[1] + xn.y,
                                 acc[2] + xn.z, acc[3] + xn.w);
        ((float4*)(g_h + (size_t)n * D))[lane] = out;
    } else {
        float2 xn = ((const float2*)(x + (size_t)n * D))[lane];
        ((float2*)(g_h + (size_t)n * D))[lane] =
            make_float2(acc[0] + xn.x, acc[1] + xn.y);
    }
}

// ---------------------------------------------------------------------------
// Fused MLP kernel (persistent blocks; K-pair-packed weights in smem, FFMA2):
//   out = relu( relu(h@W1 + b1) @ W2 + b2 ),  h read from g_h
// ---------------------------------------------------------------------------
template <int DIN>
__global__ void __launch_bounds__(256, 1) mlp_kernel(
    int os,
    const float* __restrict__ W1, const float* __restrict__ b1,
    const float* __restrict__ W2, const float* __restrict__ b2, int N_)
{
    extern __shared__ u64 smu[];
    u64* sW1p = smu;                         // (DIN/2)*128 u64
    u64* sW2p = sW1p + (DIN / 2) * 128;      // 64*128 u64
    float* sb1 = (float*)(sW2p + 64 * 128);  // 128
    float* sb2 = sb1 + 128;                  // 128
    float* sH  = sb2 + 128;                  // 64*DIN
    float* sT  = sH + 64 * DIN;              // 64*128

    int tid = threadIdx.x;
    // prepack W1 pairs over k: sW1p[k2*128+c] = (W1[2k2][c], W1[2k2+1][c])
    for (int i = tid; i < (DIN / 2) * 128; i += 256) {
        int k2 = i >> 7, c = i & 127;
        sW1p[i] = pack2(W1[(2 * k2) * 128 + c], W1[(2 * k2 + 1) * 128 + c]);
    }
    for (int i = tid; i < 64 * 128; i += 256) {
        int k2 = i >> 7, c = i & 127;
        sW2p[i] = pack2(W2[(2 * k2) * 128 + c], W2[(2 * k2 + 1) * 128 + c]);
    }
    if (tid < 128) { sb1[tid] = b1[tid]; sb2[tid] = b2[tid]; }
    __syncthreads();

    float* outp = (os == 0) ? g_hA : g_hB;

    int tx = tid & 31;   // col group: cols tx*4 .. tx*4+3
    int ty = tid >> 5;   // row group: rows ty*8 .. ty*8+7

    const int ntiles = (N_ + 63) / 64;
    for (int tile = blockIdx.x; tile < ntiles; tile += gridDim.x) {
        int base = tile * 64;

        constexpr int C4 = DIN / 4;
        for (int i4 = tid; i4 < 64 * C4; i4 += 256) {
            int r = i4 / C4;
            int c4 = i4 - r * C4;
            int gr = base + r;
            float4 v = make_float4(0.f, 0.f, 0.f, 0.f);
            if (gr < N_) v = ((const float4*)g_h)[(size_t)gr * C4 + c4];
            ((float4*)sH)[i4] = v;
        }
        __syncthreads();

        // phase 1: t = relu(h @ W1 + b1)
        {
            u64 acc[8][4];
            #pragma unroll
            for (int r = 0; r < 8; r++)
                #pragma unroll
                for (int j = 0; j < 4; j++) acc[r][j] = 0ULL;
            #pragma unroll 2
            for (int k2 = 0; k2 < DIN / 2; k2++) {
                const ulonglong2* wrow = (const ulonglong2*)(sW1p + k2 * 128);
                ulonglong2 w01 = wrow[tx * 2];
                ulonglong2 w23 = wrow[tx * 2 + 1];
                u64 w[4] = {w01.x, w01.y, w23.x, w23.y};
                u64 a[8];
                #pragma unroll
                for (int r = 0; r < 8; r++)
                    a[r] = *(const u64*)(sH + (ty * 8 + r) * DIN + 2 * k2);
                #pragma unroll
                for (int r = 0; r < 8; r++)
                    #pragma unroll
                    for (int j = 0; j < 4; j++)
                        acc[r][j] = ffma2(a[r], w[j], acc[r][j]);
            }
            float bb[4];
            #pragma unroll
            for (int j = 0; j < 4; j++) bb[j] = sb1[tx * 4 + j];
            #pragma unroll
            for (int r = 0; r < 8; r++) {
                float v[4];
                #pragma unroll
                for (int j = 0; j < 4; j++) {
                    float lo, hi;
                    unpack2(acc[r][j], lo, hi);
                    v[j] = fmaxf(lo + hi + bb[j], 0.f);
                }
                ((float4*)(sT + (ty * 8 + r) * 128))[tx] =
                    make_float4(v[0], v[1], v[2], v[3]);
            }
        }
        __syncthreads();

        // phase 2: out = relu(t @ W2 + b2)
        {
            u64 acc[8][4];
            #pragma unroll
            for (int r = 0; r < 8; r++)
                #pragma unroll
                for (int j = 0; j < 4; j++) acc[r][j] = 0ULL;
            #pragma unroll 2
            for (int k2 = 0; k2 < 64; k2++) {
                const ulonglong2* wrow = (const ulonglong2*)(sW2p + k2 * 128);
                ulonglong2 w01 = wrow[tx * 2];
                ulonglong2 w23 = wrow[tx * 2 + 1];
                u64 w[4] = {w01.x, w01.y, w23.x, w23.y};
                u64 a[8];
                #pragma unroll
                for (int r = 0; r < 8; r++)
                    a[r] = *(const u64*)(sT + (ty * 8 + r) * 128 + 2 * k2);
                #pragma unroll
                for (int r = 0; r < 8; r++)
                    #pragma unroll
                    for (int j = 0; j < 4; j++)
                        acc[r][j] = ffma2(a[r], w[j], acc[r][j]);
            }
            float bb[4];
            #pragma unroll
            for (int j = 0; j < 4; j++) bb[j] = sb2[tx * 4 + j];
            #pragma unroll
            for (int r = 0; r < 8; r++) {
                int gr = base + ty * 8 + r;
                if (gr < N_) {
                    float v[4];
                    #pragma unroll
                    for (int j = 0; j < 4; j++) {
                        float lo, hi;
                        unpack2(acc[r][j], lo, hi);
                        v[j] = fmaxf(lo + hi + bb[j], 0.f);
                    }
                    ((float4*)(outp + (size_t)gr * 128))[tx] =
                        make_float4(v[0], v[1], v[2], v[3]);
                }
            }
        }
        __syncthreads();
    }
}

// ---------------------------------------------------------------------------
// Final: out[n] = sigmoid(h[n] . Wlin + blin). One warp per node.
// ---------------------------------------------------------------------------
__global__ void __launch_bounds__(256) final_kernel(
    int hs, const float* __restrict__ Wlin, const float* __restrict__ blin,
    float* __restrict__ out, int N_)
{
    __shared__ float sw[128];
    if (threadIdx.x < 128) sw[threadIdx.x] = Wlin[threadIdx.x];
    __syncthreads();
    const float* h = (hs == 0) ? g_hA : g_hB;
    int lane = threadIdx.x & 31;
    int warp = (blockIdx.x * 256 + threadIdx.x) >> 5;
    int nw = (gridDim.x * 256) >> 5;
    float bl = blin[0];
    for (int n = warp; n < N_; n += nw) {
        float4 hv = ((const float4*)(h + (size_t)n * 128))[lane];
        float4 wv = ((const float4*)sw)[lane];
        float v = hv.x * wv.x + hv.y * wv.y + hv.z * wv.z + hv.w * wv.w;
        #pragma unroll
        for (int o = 16; o; o >>= 1) v += __shfl_xor_sync(0xFFFFFFFFu, v, o);
        if (lane == 0) out[n] = 1.f / (1.f + expf(-(v + bl)));
    }
}

// ---------------------------------------------------------------------------
extern "C" void kernel_launch(void* const* d_in, const int* in_sizes, int n_in,
                              void* d_out, int out_size)
{
    const float* x   = (const float*)d_in[0];
    const void*  ei  = d_in[1];
    const float* ea  = (const float*)d_in[2];
    const float* We0 = (const float*)d_in[3];
    const float* be0 = (const float*)d_in[4];
    const float* W10 = (const float*)d_in[5];
    const float* b10 = (const float*)d_in[6];
    const float* W20 = (const float*)d_in[7];
    const float* b20 = (const float*)d_in[8];
    const float* We1 = (const float*)d_in[9];
    const float* be1 = (const float*)d_in[10];
    const float* W11 = (const float*)d_in[11];
    const float* b11 = (const float*)d_in[12];
    const float* W21 = (const float*)d_in[13];
    const float* b21 = (const float*)d_in[14];
    const float* We2 = (const float*)d_in[15];
    const float* be2 = (const float*)d_in[16];
    const float* W12 = (const float*)d_in[17];
    const float* b12 = (const float*)d_in[18];
    const float* W22 = (const float*)d_in[19];
    const float* b22 = (const float*)d_in[20];
    const float* Wln = (const float*)d_in[21];
    const float* bln = (const float*)d_in[22];

    int N_ = in_sizes[0] / 64;
    int E_ = in_sizes[2] / 16;

    constexpr int SMEM64  = (32 * 128 + 64 * 128) * 8 + (256 + 64 * 64 + 64 * 128) * 4;
    constexpr int SMEM128 = (64 * 128 + 64 * 128) * 8 + (256 + 64 * 128 + 64 * 128) * 4;
    cudaFuncSetAttribute(mlp_kernel<64>,  cudaFuncAttributeMaxDynamicSharedMemorySize, SMEM64);
    cudaFuncSetAttribute(mlp_kernel<128>, cudaFuncAttributeMaxDynamicSharedMemorySize, SMEM128);

    int ebc = (E_ + 255) / 256;
    int nb  = (N_ + 1023) / 1024;
    int gwb = (N_ * 32 + 255) / 256;

    // ---- CSR build (once per call; ea permutation shared by all 3 layers) ----
    detect_kernel<<<1, 256>>>((const long long*)ei, E_, N_);
    zero_aux_kernel<<<(N_ + 255) / 256, 256>>>(N_);
    convert_hist_kernel<<<ebc, 256>>>(ei, E_);
    scan1_kernel<<<nb, 1024>>>(N_);
    scan2_kernel<<<1, 32>>>(nb);
    scan3_kernel<<<nb, 1024>>>(N_);
    scatter_kernel<<<ebc, 256>>>(ea, E_);

    // ---- layer 0 (d = 64) ----
    gather_kernel<64><<<gwb, 256>>>(x, 0, We0, be0, N_);
    mlp_kernel<64><<<148, 256, SMEM64>>>(/*out=hA*/0, W10, b10, W20, b20, N_);

    // ---- layer 1 (d = 128) ----
    gather_kernel<128><<<gwb, 256>>>(nullptr, /*x=hA*/0, We1, be1, N_);
    mlp_kernel<128><<<148, 256, SMEM128>>>(/*out=hB*/1, W11, b11, W21, b21, N_);

    // ---- layer 2 (d = 128) ----
    gather_kernel<128><<<gwb, 256>>>(nullptr, /*x=hB*/1, We2, be2, N_);
    mlp_kernel<128><<<148, 256, SMEM128>>>(/*out=hA*/0, W12, b12, W22, b22, N_);

    // ---- final linear + sigmoid ----
    final_kernel<<<(N_ + 7) / 8, 256>>>(0, Wln, bln, (float*)d_out, N_);
}